// round 3
// baseline (speedup 1.0000x reference)
#include <cuda_runtime.h>
#include <cuda_bf16.h>

// Per-block partial sums + completion ticket. __device__ globals are
// zero-initialized at load; g_count is reset to 0 by the last block each
// launch, so every graph replay starts from the same state (deterministic).
#define MAX_BLOCKS 4096
__device__ double g_partials[MAX_BLOCKS];
__device__ unsigned int g_count;

__device__ __forceinline__ float kl_elem(float mp, float lsp, float mq, float lsq) {
    // elem = (lsq - lsp) + exp(lsp - lsq) + (mq-mp)^2 * exp(-lsq)
    float t = lsp - lsq;
    float dz = mq - mp;
    return -t + __expf(t) + dz * dz * __expf(-lsq);
}

__global__ void __launch_bounds__(256, 8)
kl_fused_kernel(const float4* __restrict__ mp,
                const float4* __restrict__ lsp,
                const float4* __restrict__ mq,
                const float4* __restrict__ lsq,
                int n4,
                float* __restrict__ out,
                double inv_nsamples, double d_chan) {
    float sum = 0.0f;
    int idx = blockIdx.x * blockDim.x + threadIdx.x;
    int stride = gridDim.x * blockDim.x;

    // Unrolled x2: 8 independent LDG.128 in flight per iteration.
    int i = idx;
    for (; i + stride < n4; i += 2 * stride) {
        float4 a0 = __ldcs(&mp[i]);
        float4 p0 = __ldcs(&lsp[i]);
        float4 b0 = __ldcs(&mq[i]);
        float4 q0 = __ldcs(&lsq[i]);
        int j = i + stride;
        float4 a1 = __ldcs(&mp[j]);
        float4 p1 = __ldcs(&lsp[j]);
        float4 b1 = __ldcs(&mq[j]);
        float4 q1 = __ldcs(&lsq[j]);
        sum += kl_elem(a0.x, p0.x, b0.x, q0.x);
        sum += kl_elem(a0.y, p0.y, b0.y, q0.y);
        sum += kl_elem(a0.z, p0.z, b0.z, q0.z);
        sum += kl_elem(a0.w, p0.w, b0.w, q0.w);
        sum += kl_elem(a1.x, p1.x, b1.x, q1.x);
        sum += kl_elem(a1.y, p1.y, b1.y, q1.y);
        sum += kl_elem(a1.z, p1.z, b1.z, q1.z);
        sum += kl_elem(a1.w, p1.w, b1.w, q1.w);
    }
    for (; i < n4; i += stride) {
        float4 a = __ldcs(&mp[i]);
        float4 p = __ldcs(&lsp[i]);
        float4 b = __ldcs(&mq[i]);
        float4 q = __ldcs(&lsq[i]);
        sum += kl_elem(a.x, p.x, b.x, q.x);
        sum += kl_elem(a.y, p.y, b.y, q.y);
        sum += kl_elem(a.z, p.z, b.z, q.z);
        sum += kl_elem(a.w, p.w, b.w, q.w);
    }

    // Warp reduction (fp32)
    #pragma unroll
    for (int o = 16; o > 0; o >>= 1)
        sum += __shfl_xor_sync(0xFFFFFFFFu, sum, o);

    // Block reduction
    __shared__ float wsums[8];
    __shared__ bool is_last;
    int wid = threadIdx.x >> 5;
    int lid = threadIdx.x & 31;
    if (lid == 0) wsums[wid] = sum;
    __syncthreads();

    if (threadIdx.x == 0) {
        float v = 0.0f;
        #pragma unroll
        for (int w = 0; w < 8; w++) v += wsums[w];
        g_partials[blockIdx.x] = (double)v;
        __threadfence();
        unsigned int ticket = atomicAdd(&g_count, 1u);
        is_last = (ticket == gridDim.x - 1);
    }
    __syncthreads();

    // Last block: reduce all partials, write output, reset ticket.
    if (is_last) {
        double acc = 0.0;
        for (int b = threadIdx.x; b < gridDim.x; b += blockDim.x)
            acc += g_partials[b];
        #pragma unroll
        for (int o = 16; o > 0; o >>= 1)
            acc += __shfl_xor_sync(0xFFFFFFFFu, acc, o);
        __shared__ double dsums[8];
        if (lid == 0) dsums[wid] = acc;
        __syncthreads();
        if (threadIdx.x == 0) {
            double t = 0.0;
            #pragma unroll
            for (int w = 0; w < 8; w++) t += dsums[w];
            out[0] = (float)(0.5 * (t * inv_nsamples - d_chan));
            g_count = 0;  // restore state for next (graph-replayed) launch
        }
    }
}

extern "C" void kernel_launch(void* const* d_in, const int* in_sizes, int n_in,
                              void* d_out, int out_size) {
    const float4* mp  = (const float4*)d_in[0];
    const float4* lsp = (const float4*)d_in[1];
    const float4* mq  = (const float4*)d_in[2];
    const float4* lsq = (const float4*)d_in[3];
    float* out = (float*)d_out;

    const int n = in_sizes[0];          // 29,491,200 elements
    const int n4 = n / 4;
    const int d_chan = 3;               // channel dim (shape[1])
    const long long n_samples = (long long)n / d_chan;

    const int threads = 256;
    const int blocks = 148 * 16;        // 2368 <= MAX_BLOCKS

    kl_fused_kernel<<<blocks, threads>>>(mp, lsp, mq, lsq, n4, out,
                                         1.0 / (double)n_samples, (double)d_chan);
}

// round 4
// speedup vs baseline: 1.0115x; 1.0115x over previous
#include <cuda_runtime.h>
#include <cuda_bf16.h>

// Per-block partial sums + completion ticket. g_count is reset to 0 by the
// last block each launch, so every graph replay starts from identical state.
#define MAX_BLOCKS 4096
__device__ double g_partials[MAX_BLOCKS];
__device__ unsigned int g_count;

__device__ __forceinline__ float kl_elem(float mp, float lsp, float mq, float lsq) {
    // elem = (lsq - lsp) + exp(lsp - lsq) + (mq-mp)^2 * exp(-lsq)
    float t = lsp - lsq;
    float dz = mq - mp;
    return -t + __expf(t) + dz * dz * __expf(-lsq);
}

__global__ void __launch_bounds__(256, 8)
kl_fused_kernel(const float4* __restrict__ mp,
                const float4* __restrict__ lsp,
                const float4* __restrict__ mq,
                const float4* __restrict__ lsq,
                int n4,
                float* __restrict__ out,
                double inv_nsamples, double d_chan) {
    float sum = 0.0f;
    int idx = blockIdx.x * blockDim.x + threadIdx.x;
    int stride = gridDim.x * blockDim.x;

    // R2-proven streaming loop: 4 independent LDG.128 per iteration,
    // fits the 32-register budget (no spill, full MLP).
    for (int i = idx; i < n4; i += stride) {
        float4 a = __ldcs(&mp[i]);
        float4 p = __ldcs(&lsp[i]);
        float4 b = __ldcs(&mq[i]);
        float4 q = __ldcs(&lsq[i]);
        sum += kl_elem(a.x, p.x, b.x, q.x);
        sum += kl_elem(a.y, p.y, b.y, q.y);
        sum += kl_elem(a.z, p.z, b.z, q.z);
        sum += kl_elem(a.w, p.w, b.w, q.w);
    }

    // Warp reduction (fp32)
    #pragma unroll
    for (int o = 16; o > 0; o >>= 1)
        sum += __shfl_xor_sync(0xFFFFFFFFu, sum, o);

    // Block reduction
    __shared__ float wsums[8];
    __shared__ bool is_last;
    int wid = threadIdx.x >> 5;
    int lid = threadIdx.x & 31;
    if (lid == 0) wsums[wid] = sum;
    __syncthreads();

    if (threadIdx.x == 0) {
        float v = 0.0f;
        #pragma unroll
        for (int w = 0; w < 8; w++) v += wsums[w];
        g_partials[blockIdx.x] = (double)v;
        __threadfence();
        unsigned int ticket = atomicAdd(&g_count, 1u);
        is_last = (ticket == gridDim.x - 1);
    }
    __syncthreads();

    // Last block: reduce all partials, write output, reset ticket.
    if (is_last) {
        double acc = 0.0;
        for (int b = threadIdx.x; b < gridDim.x; b += blockDim.x)
            acc += g_partials[b];
        #pragma unroll
        for (int o = 16; o > 0; o >>= 1)
            acc += __shfl_xor_sync(0xFFFFFFFFu, acc, o);
        __shared__ double dsums[8];
        if (lid == 0) dsums[wid] = acc;
        __syncthreads();
        if (threadIdx.x == 0) {
            double t = 0.0;
            #pragma unroll
            for (int w = 0; w < 8; w++) t += dsums[w];
            out[0] = (float)(0.5 * (t * inv_nsamples - d_chan));
            g_count = 0;  // deterministic state for next graph replay
        }
    }
}

extern "C" void kernel_launch(void* const* d_in, const int* in_sizes, int n_in,
                              void* d_out, int out_size) {
    const float4* mp  = (const float4*)d_in[0];
    const float4* lsp = (const float4*)d_in[1];
    const float4* mq  = (const float4*)d_in[2];
    const float4* lsq = (const float4*)d_in[3];
    float* out = (float*)d_out;

    const int n = in_sizes[0];          // 29,491,200 elements
    const int n4 = n / 4;
    const int d_chan = 3;               // channel dim (shape[1])
    const long long n_samples = (long long)n / d_chan;

    const int threads = 256;
    const int blocks = 148 * 16;        // 2368 <= MAX_BLOCKS

    kl_fused_kernel<<<blocks, threads>>>(mp, lsp, mq, lsq, n4, out,
                                         1.0 / (double)n_samples, (double)d_chan);
}